// round 16
// baseline (speedup 1.0000x reference)
#include <cuda_runtime.h>
#include <cuda_bf16.h>
#include <cstdint>

#define KC 512
#define DD 64
#define HW 4096
#define NVEC 131072
#define NTH 256
#define MTILE 256
#define NTILES (NVEC / MTILE)        // 512
#define GRID 256                     // 2 tiles per CTA; 2 CTAs per SM
#define CAP 1000

#define CBROW 36                     // 32 data + cbsqr@32 + pad (4g+t bank map)
#define AROW  34                     // 32 data + thresh@32 + pad
// smem byte offsets
#define OFF_CB16 0                            // 512*36*4 = 73728
#define OFF_A16  73728                        // 256*34*4 = 34816 -> 108544
#define OFF_KEY  108544                       // 256 u64 = 2048   -> 110592
#define OFF_WL   110592                       // 1000 u32 = 4000  -> 114592
#define OFF_CNT  114592
#define OFF_MAXB 114596
#define SMEM_TOTAL 114688                     // 2 CTAs/SM

typedef unsigned long long u64;
typedef unsigned int u32;

__device__ __forceinline__ u64 ffma2(u64 a, u64 b, u64 c) {
    u64 d;
    asm("fma.rn.f32x2 %0, %1, %2, %3;" : "=l"(d) : "l"(a), "l"(b), "l"(c));
    return d;
}
__device__ __forceinline__ u64 pk(float lo, float hi) {
    u64 d;
    asm("mov.b64 %0, {%1, %2};" : "=l"(d) : "f"(lo), "f"(hi));
    return d;
}
__device__ __forceinline__ void unpack2(u64 a, float& lo, float& hi) {
    asm("mov.b64 {%0, %1}, %2;" : "=f"(lo), "=f"(hi) : "l"(a));
}
__device__ __forceinline__ u32 bf16x2(float hi, float lo) {
    u32 w;
    asm("cvt.rn.bf16x2.f32 %0, %1, %2;" : "=r"(w) : "f"(hi), "f"(lo));
    return w;
}
// Scalar tree identical to round 1 (bit-exact vs reference; rel_err 0.0).
__device__ __forceinline__ float tree8(u64 a0, u64 a1, u64 a2, u64 a3) {
    float f0, f1, f2, f3, f4, f5, f6, f7;
    unpack2(a0, f0, f1); unpack2(a1, f2, f3);
    unpack2(a2, f4, f5); unpack2(a3, f6, f7);
    return ((f0 + f1) + (f2 + f3)) + ((f4 + f5) + (f6 + f7));
}
// Exact distance: byte-identical arithmetic to round 1 (4 chains, tree, fmaf).
__device__ __forceinline__ float exact_dist(const float* __restrict__ cbrow,
                                            const u64* x2, float ckxs) {
    u64 a0 = 0, a1 = 0, a2 = 0, a3 = 0;
    const float4* c4 = (const float4*)cbrow;
    #pragma unroll
    for (int j = 0; j < 8; j++) {
        float4 lo = c4[2 * j], hi = c4[2 * j + 1];
        a0 = ffma2(x2[4 * j + 0], pk(lo.x, lo.y), a0);
        a1 = ffma2(x2[4 * j + 1], pk(lo.z, lo.w), a1);
        a2 = ffma2(x2[4 * j + 2], pk(hi.x, hi.y), a2);
        a3 = ffma2(x2[4 * j + 3], pk(hi.z, hi.w), a3);
    }
    return fmaf(-2.0f, tree8(a0, a1, a2, a3), ckxs);
}
// Reload row's x with the round-1 chain (bit-exact; proven in R14/R15).
__device__ __forceinline__ float load_x(const float* __restrict__ xq, u64* xx) {
    float xs = 0.f;
    #pragma unroll
    for (int j = 0; j < 32; j++) {
        float lo = xq[(size_t)(2 * j) * HW];
        float hi = xq[(size_t)(2 * j + 1) * HW];
        xs = fmaf(lo, lo, xs);
        xs = fmaf(hi, hi, xs);
        xx[j] = pk(lo, hi);
    }
    return xs;
}
// HMMA m16n8k16 bf16 -> f32 (plain PTX, base sm_103 target OK)
__device__ __forceinline__ void mma16816(float* d, const u32* a, u32 b0, u32 b1) {
    asm volatile(
        "mma.sync.aligned.m16n8k16.row.col.f32.bf16.bf16.f32 "
        "{%0,%1,%2,%3}, {%4,%5,%6,%7}, {%8,%9}, {%0,%1,%2,%3};"
        : "+f"(d[0]), "+f"(d[1]), "+f"(d[2]), "+f"(d[3])
        : "r"(a[0]), "r"(a[1]), "r"(a[2]), "r"(a[3]), "r"(b0), "r"(b1));
}

// Split-ks MMA body: ks{0,1} -> dXa, ks{2,3} -> dXb (4 independent chains).
// Reassociation only perturbs the APPROX dot by ~ULP f32 -- covered by the
// prune margin; pass A and pass B run identical code => identical s bits.
#define MMA_BODY(bw)                                                        \
    float d0a[4] = {0, 0, 0, 0}, d0b[4] = {0, 0, 0, 0};                     \
    float d1a[4] = {0, 0, 0, 0}, d1b[4] = {0, 0, 0, 0};                     \
    {                                                                       \
        u32 p0 = (bw)[0 * 8 + t], p1 = (bw)[0 * 8 + t + 4];                 \
        u32 q0 = (bw)[1 * 8 + t], q1 = (bw)[1 * 8 + t + 4];                 \
        u32 r0 = (bw)[2 * 8 + t], r1 = (bw)[2 * 8 + t + 4];                 \
        u32 s0_ = (bw)[3 * 8 + t], s1_ = (bw)[3 * 8 + t + 4];               \
        mma16816(d0a, af[0][0], p0, p1);                                    \
        mma16816(d0b, af[0][2], r0, r1);                                    \
        mma16816(d1a, af[1][0], p0, p1);                                    \
        mma16816(d1b, af[1][2], r0, r1);                                    \
        mma16816(d0a, af[0][1], q0, q1);                                    \
        mma16816(d0b, af[0][3], s0_, s1_);                                  \
        mma16816(d1a, af[1][1], q0, q1);                                    \
        mma16816(d1b, af[1][3], s0_, s1_);                                  \
    }                                                                       \
    float e0 = d0a[0] + d0b[0], e1 = d0a[1] + d0b[1];                       \
    float e2 = d0a[2] + d0b[2], e3 = d0a[3] + d0b[3];                       \
    float e4 = d1a[0] + d1b[0], e5 = d1a[1] + d1b[1];                       \
    float e6 = d1a[2] + d1b[2], e7 = d1a[3] + d1b[3];

__global__ void __launch_bounds__(NTH, 2)
vq_kernel(const float* __restrict__ ze, const float* __restrict__ cbg,
          float* __restrict__ out, int write2) {
    extern __shared__ char smem[];
    u32*   cb16 = (u32*)(smem + OFF_CB16);   // [512][36], cbsqr at col 32
    u32*   a16  = (u32*)(smem + OFF_A16);    // [256][34], thresh at col 32
    float* a16f = (float*)(smem + OFF_A16);
    u64*   key  = (u64*)(smem + OFF_KEY);    // [256]
    u32*   wl   = (u32*)(smem + OFF_WL);     // [CAP]
    int*   cnt  = (int*)(smem + OFF_CNT);
    int*   maxb = (int*)(smem + OFF_MAXB);

    const int tid = threadIdx.x;
    const int wid = tid >> 5;
    const int lane = tid & 31;
    const int g = lane >> 2;
    const int t = lane & 3;
    const int wbase = wid * 32;
    const int m = tid;

    // ---- setup: codebook bf16 + cbsqr packed in row padding ----
    if (tid == 0) *maxb = 0;
    __syncthreads();
    for (int idx = tid; idx < KC * 32; idx += NTH) {
        int row = idx >> 5, j = idx & 31;
        float lo = cbg[row * DD + 2 * j], hi = cbg[row * DD + 2 * j + 1];
        cb16[row * CBROW + j] = bf16x2(hi, lo);
    }
    for (int k = tid; k < KC; k += NTH) {
        const float* row = cbg + k * DD;
        float s = 0.f;
        #pragma unroll
        for (int d = 0; d < DD; d++) s = fmaf(row[d], row[d], s);
        cb16[k * CBROW + 32] = __float_as_uint(s);
        atomicMax(maxb, __float_as_int(s));   // s > 0: bits monotone
    }
    __syncthreads();
    const float cmax = sqrtf(__int_as_float(*maxb)) * 1.0002f;

    for (int tile = blockIdx.x; tile < NTILES; tile += GRID) {
        const int btile = (tile * MTILE) >> 12;        // whole tile shares b
        const int stile = (tile * MTILE) & 4095;
        const float* xp = ze + (size_t)btile * (DD * HW) + stile + m;

        key[m] = ~0ull;
        if (tid == 0) *cnt = 0;

        // ---- load x (round-1 chain), write bf16 A row ----
        float xsqr = 0.f;
        {
            u32* arow = a16 + m * AROW;
            #pragma unroll
            for (int j = 0; j < 32; j++) {
                float lo = xp[(size_t)(2 * j) * HW];
                float hi = xp[(size_t)(2 * j + 1) * HW];
                xsqr = fmaf(lo, lo, xsqr);
                xsqr = fmaf(hi, hi, xsqr);
                arow[j] = bf16x2(hi, lo);
            }
        }
        __syncthreads();   // A visible; cnt/key init visible CTA-wide

        // ---- register A fragments (warp-private rows) ----
        u32 af[2][4][4];
        #pragma unroll
        for (int mt = 0; mt < 2; mt++) {
            const u32* r0 = a16 + (wbase + mt * 16 + g) * AROW;
            const u32* r1 = r0 + 8 * AROW;
            #pragma unroll
            for (int ks = 0; ks < 4; ks++) {
                af[mt][ks][0] = r0[ks * 8 + t];
                af[mt][ks][1] = r1[ks * 8 + t];
                af[mt][ks][2] = r0[ks * 8 + t + 4];
                af[mt][ks][3] = r1[ks * 8 + t + 4];
            }
        }

        // ---- pass A: min of raw f32 s = ck - 2 dot (no storage) ----
        float mn0 = 3.4e38f, mn1 = 3.4e38f, mn2 = 3.4e38f, mn3 = 3.4e38f;
        #pragma unroll 2
        for (int nt = 0; nt < 64; nt++) {
            const u32* bw = cb16 + (nt * 8 + g) * CBROW;
            MMA_BODY(bw)
            const int k0 = nt * 8 + 2 * t;
            float ckx = __uint_as_float(cb16[k0 * CBROW + 32]);
            float cky = __uint_as_float(cb16[(k0 + 1) * CBROW + 32]);
            mn0 = fminf(mn0, fminf(fmaf(-2.f, e0, ckx), fmaf(-2.f, e1, cky)));
            mn1 = fminf(mn1, fminf(fmaf(-2.f, e2, ckx), fmaf(-2.f, e3, cky)));
            mn2 = fminf(mn2, fminf(fmaf(-2.f, e4, ckx), fmaf(-2.f, e5, cky)));
            mn3 = fminf(mn3, fminf(fmaf(-2.f, e6, ckx), fmaf(-2.f, e7, cky)));
        }
        #pragma unroll
        for (int d = 1; d < 4; d <<= 1) {
            mn0 = fminf(mn0, __shfl_xor_sync(0xffffffffu, mn0, d));
            mn1 = fminf(mn1, __shfl_xor_sync(0xffffffffu, mn1, d));
            mn2 = fminf(mn2, __shfl_xor_sync(0xffffffffu, mn2, d));
            mn3 = fminf(mn3, __shfl_xor_sync(0xffffffffu, mn3, d));
        }
        if (t == 0) {
            a16f[(wbase + g +  0) * AROW + 32] = mn0;
            a16f[(wbase + g +  8) * AROW + 32] = mn1;
            a16f[(wbase + g + 16) * AROW + 32] = mn2;
            a16f[(wbase + g + 24) * AROW + 32] = mn3;
        }
        __syncwarp();
        // row m's threshold (margin proven in R13-R15)
        {
            float rowmin = a16f[m * AROW + 32];
            a16f[m * AROW + 32] =
                rowmin + fmaf(0.06f * cmax, sqrtf(xsqr), 2e-4f);
        }
        __syncwarp();
        const float th0 = a16f[(wbase + g +  0) * AROW + 32];
        const float th1 = a16f[(wbase + g +  8) * AROW + 32];
        const float th2 = a16f[(wbase + g + 16) * AROW + 32];
        const float th3 = a16f[(wbase + g + 24) * AROW + 32];

        // ---- pass B: identical MMA recompute; push candidates ----
        #pragma unroll 2
        for (int nt = 0; nt < 64; nt++) {
            const u32* bw = cb16 + (nt * 8 + g) * CBROW;
            MMA_BODY(bw)
            const int k0 = nt * 8 + 2 * t;
            float ckx = __uint_as_float(cb16[k0 * CBROW + 32]);
            float cky = __uint_as_float(cb16[(k0 + 1) * CBROW + 32]);
            float s0 = fmaf(-2.f, e0, ckx), s1 = fmaf(-2.f, e1, cky);
            float s2 = fmaf(-2.f, e2, ckx), s3 = fmaf(-2.f, e3, cky);
            float s4 = fmaf(-2.f, e4, ckx), s5 = fmaf(-2.f, e5, cky);
            float s6 = fmaf(-2.f, e6, ckx), s7 = fmaf(-2.f, e7, cky);
            #define PUSH(cond, row, kk)                                     \
                if (cond) {                                                 \
                    int i = atomicAdd(cnt, 1);                              \
                    if (i < CAP) wl[i] = ((u32)(row) << 9) | (u32)(kk);     \
                }
            PUSH(s0 <= th0, wbase + g,      k0);
            PUSH(s1 <= th0, wbase + g,      k0 + 1);
            PUSH(s2 <= th1, wbase + g + 8,  k0);
            PUSH(s3 <= th1, wbase + g + 8,  k0 + 1);
            PUSH(s4 <= th2, wbase + g + 16, k0);
            PUSH(s5 <= th2, wbase + g + 16, k0 + 1);
            PUSH(s6 <= th3, wbase + g + 24, k0);
            PUSH(s7 <= th3, wbase + g + 24, k0 + 1);
            #undef PUSH
        }
        __syncthreads();   // worklist complete

        const int count = *cnt;
        if (count <= CAP) {
            // batch-parallel exact refine (bit-exact; ties -> smaller k)
            for (int i = tid; i < count; i += NTH) {
                u32 e = wl[i];
                int row = (int)(e >> 9);
                int k   = (int)(e & 511u);
                u64 xx[32];
                float xs = load_x(ze + (size_t)btile * (DD * HW) + stile + row, xx);
                float ck = __uint_as_float(cb16[k * CBROW + 32]);
                float d  = exact_dist(cbg + (size_t)k * DD, xx, ck + xs);
                u64 kk = ((u64)((u32)__float_as_int(d)) << 9) | (u32)k;
                atomicMin((unsigned long long*)&key[row], kk);
            }
        } else {
            // overflow fallback (never expected): full exact scan, own row
            u64 xx[32];
            float xs = load_x(xp, xx);
            float best = 3.4028235e38f;
            int bestk = 0;
            for (int k = 0; k < KC; k++) {
                float ck = __uint_as_float(cb16[k * CBROW + 32]);
                float d = exact_dist(cbg + (size_t)k * DD, xx, ck + xs);
                if (d < best) { best = d; bestk = k; }
            }
            key[m] = ((u64)((u32)__float_as_int(best)) << 9) | (u32)bestk;
        }
        __syncthreads();   // keys final

        // ---- scatter winning f32 code row to both outputs (NCHW) ----
        const int bestk = (int)(key[m] & 511u);
        const float4* code4 = (const float4*)(cbg + (size_t)bestk * DD);
        float* o1 = out + (size_t)btile * (DD * HW) + stile + m;
        float* o2 = o1 + (size_t)NVEC * DD;
        if (write2) {
            #pragma unroll
            for (int q = 0; q < 16; q++) {
                float4 w = code4[q];
                o1[(size_t)(4 * q + 0) * HW] = w.x;
                o1[(size_t)(4 * q + 1) * HW] = w.y;
                o1[(size_t)(4 * q + 2) * HW] = w.z;
                o1[(size_t)(4 * q + 3) * HW] = w.w;
                o2[(size_t)(4 * q + 0) * HW] = w.x;
                o2[(size_t)(4 * q + 1) * HW] = w.y;
                o2[(size_t)(4 * q + 2) * HW] = w.z;
                o2[(size_t)(4 * q + 3) * HW] = w.w;
            }
        } else {
            #pragma unroll
            for (int q = 0; q < 16; q++) {
                float4 w = code4[q];
                o1[(size_t)(4 * q + 0) * HW] = w.x;
                o1[(size_t)(4 * q + 1) * HW] = w.y;
                o1[(size_t)(4 * q + 2) * HW] = w.z;
                o1[(size_t)(4 * q + 3) * HW] = w.w;
            }
        }
        __syncthreads();   // key/wl reads done before next tile's init
    }
}

extern "C" void kernel_launch(void* const* d_in, const int* in_sizes, int n_in,
                              void* d_out, int out_size) {
    const float* ze  = (const float*)d_in[0];   // z_e_x [32,64,64,64] f32
    const float* cbg = (const float*)d_in[1];   // codebook [512,64] f32
    float* out = (float*)d_out;
    const int write2 = (out_size >= 2 * NVEC * DD) ? 1 : 0;
    cudaFuncSetAttribute(vq_kernel, cudaFuncAttributeMaxDynamicSharedMemorySize,
                         SMEM_TOTAL);
    vq_kernel<<<GRID, NTH, SMEM_TOTAL>>>(ze, cbg, out, write2);
}